// round 14
// baseline (speedup 1.0000x reference)
#include <cuda_runtime.h>
#include <cuda_fp16.h>
#include <math.h>
#include <stdint.h>

#define N 4096
#define NSTG 64               /* K / 64, full K per CTA */
#define SCOLS 260             /* padded tile width for preB path */

// ---------------- device scratch (no allocations allowed) ----------------
__device__ uint32_t g_A[(size_t)256 * 256 * 32 * 4];   // 32 MB
__device__ uint32_t g_B[(size_t)512 * 256 * 32 * 2];   // 32 MB
__device__ float g_cipart[8][N];   // partial W2 @ b1 (per kg)
__device__ float g_mpart[32][N];   // per-nb partial of sum_j M_ij c_j
__device__ float g_rpart[32][N];   // per-nb partial of sum_j |M_ij| h_j
__device__ int g_ctr = 0;          // last-block election counter

// ---------------- helpers ----------------
__device__ __forceinline__ uint32_t smem_u32(const void *p) {
    uint32_t a;
    asm("{ .reg .u64 t; cvta.to.shared.u64 t, %1; cvt.u32.u64 %0, t; }" : "=r"(a) : "l"(p));
    return a;
}
__device__ __forceinline__ void cpasync16(uint32_t dst, const void *src) {
    asm volatile("cp.async.cg.shared.global [%0], [%1], 16;" :: "r"(dst), "l"(src) : "memory");
}
__device__ __forceinline__ void lds128(uint32_t *r, uint32_t a) {
    asm volatile("ld.shared.v4.b32 {%0,%1,%2,%3}, [%4];"
                 : "=r"(r[0]), "=r"(r[1]), "=r"(r[2]), "=r"(r[3]) : "r"(a));
}
__device__ __forceinline__ void lds64(uint32_t *r, uint32_t a) {
    asm volatile("ld.shared.v2.b32 {%0,%1}, [%2];" : "=r"(r[0]), "=r"(r[1]) : "r"(a));
}
__device__ __forceinline__ void mma16(float *d, const uint32_t *a, const uint32_t *b) {
    asm volatile(
        "mma.sync.aligned.m16n8k16.row.col.f32.f16.f16.f32 "
        "{%0,%1,%2,%3}, {%4,%5,%6,%7}, {%8,%9}, {%0,%1,%2,%3};"
        : "+f"(d[0]), "+f"(d[1]), "+f"(d[2]), "+f"(d[3])
        : "r"(a[0]), "r"(a[1]), "r"(a[2]), "r"(a[3]), "r"(b[0]), "r"(b[1]));
}
__device__ __forceinline__ uint32_t pack_h2(float lo, float hi) {
    __half2 h = __halves2half2(__float2half_rn(lo), __float2half_rn(hi));
    return *(uint32_t *)&h;
}
__device__ __forceinline__ void stg_cs4(float4 *p, float4 v) {
    asm volatile("st.global.cs.v4.f32 [%0], {%1,%2,%3,%4};"
                 :: "l"(p), "f"(v.x), "f"(v.y), "f"(v.z), "f"(v.w) : "memory");
}

// ---- k_pre: merged preprocessing, interleaved block types ---------------
// even blocks: preA — W2 -> A image (direct gather) + partial W2@b1
// odd blocks:  preB — W1 -> B image via SMEM tile
__global__ __launch_bounds__(256) void k_pre(const float *__restrict__ W2,
                                             const float *__restrict__ b1,
                                             const float *__restrict__ W1) {
    __shared__ float s[32][SCOLS];
    const int b = blockIdx.x, tid = threadIdx.x;
    const int lane = tid & 31, w = tid >> 5;

    if ((b & 1) == 0) {
        // ---------------- preA path ----------------
        int idx = b >> 1;
        int mt = idx >> 3, kg = idx & 7;
        size_t base = ((size_t)mt * 256 + kg * 32) * 128;
#pragma unroll
        for (int it = 0; it < 16; ++it) {
            int o = tid + it * 256;
            int ktl = o >> 7;
            int rem = o & 127;
            int ln = rem >> 2;
            int reg = rem & 3;
            int g = ln >> 2, t4 = ln & 3;
            int row = mt * 16 + g + (reg & 1) * 8;
            int col = kg * 512 + ktl * 16 + 2 * t4 + (reg >> 1) * 8;
            float2 v = *(const float2 *)&W2[(size_t)row * N + col];
            g_A[base + o] = pack_h2(v.x, v.y);
        }
        // fused partial ci = W2 @ b1: warp w owns rows 2w,2w+1
        float bv[16];
#pragma unroll
        for (int i = 0; i < 16; ++i)
            bv[i] = b1[kg * 512 + lane + 32 * i];
#pragma unroll
        for (int rr = 0; rr < 2; ++rr) {
            int row = 2 * w + rr;
            const float *wr = &W2[(size_t)(mt * 16 + row) * N + kg * 512];
            float s1 = 0.f;
#pragma unroll
            for (int i = 0; i < 16; ++i)
                s1 += wr[lane + 32 * i] * bv[i];
#pragma unroll
            for (int m = 1; m < 32; m <<= 1)
                s1 += __shfl_xor_sync(0xffffffffu, s1, m);
            if (lane == 0) g_cipart[kg][mt * 16 + row] = s1;
        }
    } else {
        // ---------------- preB path ----------------
        int idx = b >> 1;
        int kg = idx >> 4, ng = idx & 15;
        for (int i = tid; i < 2048; i += 256) {
            int row = i >> 6, c4 = (i & 63) * 4;
            *(float4 *)&s[row][c4] =
                *(const float4 *)&W1[(size_t)(kg * 32 + row) * N + ng * 256 + c4];
        }
        __syncthreads();
#pragma unroll
        for (int it = 0; it < 16; ++it) {
            int o = tid + it * 256;
            int ntl = o >> 7;
            int rem = o & 127;
            int ktl = rem >> 6;
            int ln = (rem >> 1) & 31;
            int reg = o & 1;
            int g = ln >> 2, t4 = ln & 3;
            int k0 = ktl * 16 + 2 * t4 + reg * 8;
            int n = ntl * 8 + g;
            g_B[((((size_t)(ng * 32 + ntl)) * 256 + kg * 2 + ktl) * 32 + ln) * 2 + reg] =
                pack_h2(s[k0][n], s[k0 + 1][n]);
        }
    }
}

// ---------------- main GEMM: round-7 core + fused epilogue + finalize ----
#define STG_BYTES 32768        /* A 16K + B 16K */
#define GS_H   (3 * STG_BYTES)
#define GS_C   (GS_H + 512)
#define GS_RED  (GS_C + 512)
#define GS_RED2 (GS_RED + 2048)
#define GS_FLAG (GS_RED2 + 2048)
#define GSMEM   (GS_FLAG + 16)

__device__ __forceinline__ void issue_stage(int s, int mb, int nb,
                                            uint32_t st, int tid) {
    int mt = tid >> 5, ia = tid & 31;
    const uint32_t *srcA = &g_A[(((size_t)(mb * 8 + mt) * 256 + s * 4) * 32) * 4];
    uint32_t dA = st + mt * 2048;
#pragma unroll
    for (int r = 0; r < 4; ++r)
        cpasync16(dA + r * 512 + ia * 16, srcA + r * 128 + ia * 4);
    int nt = tid >> 4, ib = tid & 15;
    const uint32_t *srcB = &g_B[(((size_t)(nb * 16 + nt) * 256 + s * 4) * 32) * 2];
    uint32_t dB = st + 16384 + nt * 1024;
#pragma unroll
    for (int r = 0; r < 4; ++r)
        cpasync16(dB + r * 256 + ib * 16, srcB + r * 64 + ib * 4);
    asm volatile("cp.async.commit_group;" ::: "memory");
}

__global__ __launch_bounds__(256, 2) void k_gemm(const float *__restrict__ lb0,
                                                 const float *__restrict__ ub0,
                                                 const float *__restrict__ raw_alpha,
                                                 const float *__restrict__ b2,
                                                 float *__restrict__ out,
                                                 long n4) {
    extern __shared__ __align__(16) char sm[];
    uint32_t sb = smem_u32(sm);
    const int tid = threadIdx.x, lane = tid & 31, wid = tid >> 5;
    const int wn = wid & 3, wm = wid >> 2;
    const int nb = blockIdx.x, mb = blockIdx.y;
    float4 *out4 = (float4 *)out;
    float *h = (float *)(sm + GS_H);
    float *c = (float *)(sm + GS_C);
    float *red = (float *)(sm + GS_RED);
    float *red2 = (float *)(sm + GS_RED2);
    int *flag = (int *)(sm + GS_FLAG);
    if (tid < 128) {
        float l = lb0[nb * 128 + tid], u = ub0[nb * 128 + tid];
        h[tid] = 0.5f * (u - l);
        c[tid] = 0.5f * (u + l);
    }

    float acc[4][4][4];
#pragma unroll
    for (int a = 0; a < 4; ++a)
#pragma unroll
        for (int b = 0; b < 4; ++b)
#pragma unroll
            for (int cc = 0; cc < 4; ++cc) acc[a][b][cc] = 0.f;

    issue_stage(0, mb, nb, sb + 0 * STG_BYTES, tid);
    issue_stage(1, mb, nb, sb + 1 * STG_BYTES, tid);

    // fused zeroing of the output buffer (DRAM idle during GEMM; .cs =
    // evict-first, keeps the L2-resident A/B images intact)
    {
        long base = ((long)(mb * 32 + nb) * 256 + tid);
        long stride = 1024L * 256;
        float4 z = make_float4(0.f, 0.f, 0.f, 0.f);
        for (long i = base; i < n4; i += stride) stg_cs4(&out4[i], z);
    }

    for (int s = 0; s < NSTG; ++s) {
        if (s < NSTG - 1) {
            asm volatile("cp.async.wait_group 1;" ::: "memory");
        } else {
            asm volatile("cp.async.wait_group 0;" ::: "memory");
        }
        // single barrier: stage s data visible AND all warps done with
        // compute(s-1), whose buffer (s-1)%3 == (s+2)%3 is refilled below.
        __syncthreads();
        uint32_t st = sb + (s % 3) * STG_BYTES;
        uint32_t aBase = st, bBase = st + 16384;
#pragma unroll
        for (int kk = 0; kk < 4; ++kk) {
            uint32_t af[4][4], bf[4][2];
#pragma unroll
            for (int mt = 0; mt < 4; ++mt)
                lds128(af[mt], aBase + (((wm * 4 + mt) * 4 + kk) * 32 + lane) * 16);
#pragma unroll
            for (int nt = 0; nt < 4; ++nt)
                lds64(bf[nt], bBase + (((wn * 4 + nt) * 4 + kk) * 32 + lane) * 8);
#pragma unroll
            for (int mt = 0; mt < 4; ++mt)
#pragma unroll
                for (int nt = 0; nt < 4; ++nt)
                    mma16(acc[mt][nt], af[mt], bf[nt]);
            if (kk == 0 && s + 2 < NSTG)
                issue_stage(s + 2, mb, nb, sb + ((s + 2) % 3) * STG_BYTES, tid);
        }
    }
    __syncthreads();

    // epilogue: weighted abs row-reduction (r) AND signed M@c (mid) fused
    const int tig = lane & 3, gp = lane >> 2;
#pragma unroll
    for (int mt = 0; mt < 4; ++mt)
#pragma unroll
        for (int hf = 0; hf < 2; ++hf) {
            float p = 0.f, pm = 0.f;
#pragma unroll
            for (int nt = 0; nt < 4; ++nt) {
                int n0 = wn * 32 + nt * 8 + 2 * tig;
                float v0 = acc[mt][nt][hf * 2 + 0];
                float v1 = acc[mt][nt][hf * 2 + 1];
                p += fabsf(v0) * h[n0] + fabsf(v1) * h[n0 + 1];
                pm += v0 * c[n0] + v1 * c[n0 + 1];
            }
            p += __shfl_xor_sync(0xffffffffu, p, 1);
            p += __shfl_xor_sync(0xffffffffu, p, 2);
            pm += __shfl_xor_sync(0xffffffffu, pm, 1);
            pm += __shfl_xor_sync(0xffffffffu, pm, 2);
            if (tig == 0) {
                int idx = (wm * 64 + mt * 16 + hf * 8 + gp) * 4 + wn;
                red[idx] = p;
                red2[idx] = pm;
            }
        }
    __syncthreads();
    if (tid < 128) {
        float vr = red[tid * 4 + 0] + red[tid * 4 + 1] + red[tid * 4 + 2] + red[tid * 4 + 3];
        float vm = red2[tid * 4 + 0] + red2[tid * 4 + 1] + red2[tid * 4 + 2] + red2[tid * 4 + 3];
        g_rpart[nb][mb * 128 + tid] = vr;
        g_mpart[nb][mb * 128 + tid] = vm;
    }

    // ---- last-block fused finalize (threadfence-reduction pattern) ----
    __threadfence();   // rpart/mpart AND the .cs zero-stores above are visible
    __syncthreads();
    if (tid == 0) {
        int prev = atomicAdd(&g_ctr, 1);
        flag[0] = (prev == 32 * 32 - 1);
    }
    __syncthreads();
    if (!flag[0]) return;
    __threadfence();   // acquire: all 1023 other CTAs' writes are visible

    const long NN = (long)N * N;
#pragma unroll
    for (int q = 0; q < 16; ++q) {
        int i = tid + q * 256;
        float r = 0.f, mid = b2[i];
#pragma unroll
        for (int s = 0; s < 32; ++s) {
            r += g_rpart[s][i];
            mid += g_mpart[s][i];
        }
#pragma unroll
        for (int s = 0; s < 8; ++s) mid += g_cipart[s][i];
        float lb = mid - r;
        float ub = mid + r;
        float denom = ub - lb;
        float rs = (denom == 0.f) ? 0.f : ub / denom;
        float rint = (1.f - rs) * ub;
        bool below = (ub <= 0.f);
        bool above = (lb >= 0.f);
        bool crossing = !(below || above);
        float base = above ? 1.f : 0.f;
        float uslope = crossing ? rs : base;
        float uint_ = crossing ? rint : 0.f;
        float v1 = crossing ? 0.f : base;
        float v2 = crossing ? 1.f : base;
        float alpha = 1.f / (1.f + expf(-raw_alpha[i]));
        float lslope = alpha * v1 + (1.f - alpha) * v2;

        out[(long)i * N + i] = lslope;               // diag(lslope)
        /* lintercept stays zero */
        out[NN + N + (long)i * N + i] = uslope;      // diag(uslope)
        out[2 * NN + N + i] = uint_;                 // uintercept
    }
    __syncthreads();
    if (tid == 0) g_ctr = 0;   // reset for next graph replay (deterministic)
}

// --------------------------------------------------------------------------
extern "C" void kernel_launch(void *const *d_in, const int *in_sizes, int n_in,
                              void *d_out, int out_size) {
    const float *raw_alpha = (const float *)d_in[0];
    const float *lb0 = (const float *)d_in[1];
    const float *ub0 = (const float *)d_in[2];
    const float *W1 = (const float *)d_in[3];
    const float *b1 = (const float *)d_in[4];
    const float *W2 = (const float *)d_in[5];
    const float *b2 = (const float *)d_in[6];
    float *out = (float *)d_out;

    cudaFuncSetAttribute(k_gemm, cudaFuncAttributeMaxDynamicSharedMemorySize, GSMEM);

    k_pre<<<4096, 256>>>(W2, b1, W1);
    dim3 gg(32, 32);
    k_gemm<<<gg, 256, GSMEM>>>(lb0, ub0, raw_alpha, b2, out, (long)out_size / 4);
}

// round 15
// speedup vs baseline: 1.0882x; 1.0882x over previous
#include <cuda_runtime.h>
#include <cuda_fp16.h>
#include <math.h>
#include <stdint.h>

#define N 4096
#define NSTG 64               /* K / 64, full K per CTA */
#define SCOLS 260             /* padded tile width for preB path */

// ---------------- device scratch (no allocations allowed) ----------------
__device__ uint32_t g_A[(size_t)256 * 256 * 32 * 4];   // 32 MB
__device__ uint32_t g_B[(size_t)512 * 256 * 32 * 2];   // 32 MB
__device__ float g_cipart[8][N];   // partial W2 @ b1 (per kg)
__device__ float g_mpart[32][N];   // per-nb partial of sum_j M_ij c_j
__device__ float g_rpart[32][N];   // per-nb partial of sum_j |M_ij| h_j

// ---------------- helpers ----------------
__device__ __forceinline__ uint32_t smem_u32(const void *p) {
    uint32_t a;
    asm("{ .reg .u64 t; cvta.to.shared.u64 t, %1; cvt.u32.u64 %0, t; }" : "=r"(a) : "l"(p));
    return a;
}
__device__ __forceinline__ void cpasync16(uint32_t dst, const void *src) {
    asm volatile("cp.async.cg.shared.global [%0], [%1], 16;" :: "r"(dst), "l"(src) : "memory");
}
__device__ __forceinline__ void lds128(uint32_t *r, uint32_t a) {
    asm volatile("ld.shared.v4.b32 {%0,%1,%2,%3}, [%4];"
                 : "=r"(r[0]), "=r"(r[1]), "=r"(r[2]), "=r"(r[3]) : "r"(a));
}
__device__ __forceinline__ void lds64(uint32_t *r, uint32_t a) {
    asm volatile("ld.shared.v2.b32 {%0,%1}, [%2];" : "=r"(r[0]), "=r"(r[1]) : "r"(a));
}
__device__ __forceinline__ void mma16(float *d, const uint32_t *a, const uint32_t *b) {
    asm volatile(
        "mma.sync.aligned.m16n8k16.row.col.f32.f16.f16.f32 "
        "{%0,%1,%2,%3}, {%4,%5,%6,%7}, {%8,%9}, {%0,%1,%2,%3};"
        : "+f"(d[0]), "+f"(d[1]), "+f"(d[2]), "+f"(d[3])
        : "r"(a[0]), "r"(a[1]), "r"(a[2]), "r"(a[3]), "r"(b[0]), "r"(b[1]));
}
__device__ __forceinline__ uint32_t pack_h2(float lo, float hi) {
    __half2 h = __halves2half2(__float2half_rn(lo), __float2half_rn(hi));
    return *(uint32_t *)&h;
}
__device__ __forceinline__ void stg_cs4(float4 *p, float4 v) {
    asm volatile("st.global.cs.v4.f32 [%0], {%1,%2,%3,%4};"
                 :: "l"(p), "f"(v.x), "f"(v.y), "f"(v.z), "f"(v.w) : "memory");
}

// ---- k_pre: merged preprocessing, interleaved block types ---------------
// even blocks: preA — W2 -> A image (direct gather) + partial W2@b1
// odd blocks:  preB — W1 -> B image via SMEM tile
__global__ __launch_bounds__(256) void k_pre(const float *__restrict__ W2,
                                             const float *__restrict__ b1,
                                             const float *__restrict__ W1) {
    __shared__ float s[32][SCOLS];
    const int b = blockIdx.x, tid = threadIdx.x;
    const int lane = tid & 31, w = tid >> 5;

    if ((b & 1) == 0) {
        // ---------------- preA path ----------------
        int idx = b >> 1;
        int mt = idx >> 3, kg = idx & 7;
        size_t base = ((size_t)mt * 256 + kg * 32) * 128;
#pragma unroll
        for (int it = 0; it < 16; ++it) {
            int o = tid + it * 256;
            int ktl = o >> 7;
            int rem = o & 127;
            int ln = rem >> 2;
            int reg = rem & 3;
            int g = ln >> 2, t4 = ln & 3;
            int row = mt * 16 + g + (reg & 1) * 8;
            int col = kg * 512 + ktl * 16 + 2 * t4 + (reg >> 1) * 8;
            float2 v = *(const float2 *)&W2[(size_t)row * N + col];
            g_A[base + o] = pack_h2(v.x, v.y);
        }
        // fused partial ci = W2 @ b1: warp w owns rows 2w,2w+1
        float bv[16];
#pragma unroll
        for (int i = 0; i < 16; ++i)
            bv[i] = b1[kg * 512 + lane + 32 * i];
#pragma unroll
        for (int rr = 0; rr < 2; ++rr) {
            int row = 2 * w + rr;
            const float *wr = &W2[(size_t)(mt * 16 + row) * N + kg * 512];
            float s1 = 0.f;
#pragma unroll
            for (int i = 0; i < 16; ++i)
                s1 += wr[lane + 32 * i] * bv[i];
#pragma unroll
            for (int m = 1; m < 32; m <<= 1)
                s1 += __shfl_xor_sync(0xffffffffu, s1, m);
            if (lane == 0) g_cipart[kg][mt * 16 + row] = s1;
        }
    } else {
        // ---------------- preB path ----------------
        int idx = b >> 1;
        int kg = idx >> 4, ng = idx & 15;
        for (int i = tid; i < 2048; i += 256) {
            int row = i >> 6, c4 = (i & 63) * 4;
            *(float4 *)&s[row][c4] =
                *(const float4 *)&W1[(size_t)(kg * 32 + row) * N + ng * 256 + c4];
        }
        __syncthreads();
#pragma unroll
        for (int it = 0; it < 16; ++it) {
            int o = tid + it * 256;
            int ntl = o >> 7;
            int rem = o & 127;
            int ktl = rem >> 6;
            int ln = (rem >> 1) & 31;
            int reg = o & 1;
            int g = ln >> 2, t4 = ln & 3;
            int k0 = ktl * 16 + 2 * t4 + reg * 8;
            int n = ntl * 8 + g;
            g_B[((((size_t)(ng * 32 + ntl)) * 256 + kg * 2 + ktl) * 32 + ln) * 2 + reg] =
                pack_h2(s[k0][n], s[k0 + 1][n]);
        }
    }
}

// ---------------- main GEMM: round-7 core + M@c fused epilogue -----------
#define STG_BYTES 32768        /* A 16K + B 16K */
#define GS_H   (3 * STG_BYTES)
#define GS_C   (GS_H + 512)
#define GS_RED  (GS_C + 512)
#define GS_RED2 (GS_RED + 2048)
#define GSMEM   (GS_RED2 + 2048)

__device__ __forceinline__ void issue_stage(int s, int mb, int nb,
                                            uint32_t st, int tid) {
    int mt = tid >> 5, ia = tid & 31;
    const uint32_t *srcA = &g_A[(((size_t)(mb * 8 + mt) * 256 + s * 4) * 32) * 4];
    uint32_t dA = st + mt * 2048;
#pragma unroll
    for (int r = 0; r < 4; ++r)
        cpasync16(dA + r * 512 + ia * 16, srcA + r * 128 + ia * 4);
    int nt = tid >> 4, ib = tid & 15;
    const uint32_t *srcB = &g_B[(((size_t)(nb * 16 + nt) * 256 + s * 4) * 32) * 2];
    uint32_t dB = st + 16384 + nt * 1024;
#pragma unroll
    for (int r = 0; r < 4; ++r)
        cpasync16(dB + r * 256 + ib * 16, srcB + r * 64 + ib * 4);
    asm volatile("cp.async.commit_group;" ::: "memory");
}

__global__ __launch_bounds__(256, 2) void k_gemm(const float *__restrict__ lb0,
                                                 const float *__restrict__ ub0,
                                                 float4 *__restrict__ out4,
                                                 long n4) {
    extern __shared__ __align__(16) char sm[];
    uint32_t sb = smem_u32(sm);
    const int tid = threadIdx.x, lane = tid & 31, wid = tid >> 5;
    const int wn = wid & 3, wm = wid >> 2;
    const int nb = blockIdx.x, mb = blockIdx.y;
    float *h = (float *)(sm + GS_H);
    float *c = (float *)(sm + GS_C);
    float *red = (float *)(sm + GS_RED);
    float *red2 = (float *)(sm + GS_RED2);
    if (tid < 128) {
        float l = lb0[nb * 128 + tid], u = ub0[nb * 128 + tid];
        h[tid] = 0.5f * (u - l);
        c[tid] = 0.5f * (u + l);
    }

    float acc[4][4][4];
#pragma unroll
    for (int a = 0; a < 4; ++a)
#pragma unroll
        for (int b = 0; b < 4; ++b)
#pragma unroll
            for (int cc = 0; cc < 4; ++cc) acc[a][b][cc] = 0.f;

    issue_stage(0, mb, nb, sb + 0 * STG_BYTES, tid);
    issue_stage(1, mb, nb, sb + 1 * STG_BYTES, tid);

    // fused zeroing of the output buffer (DRAM idle during GEMM; .cs =
    // evict-first, keeps the L2-resident A/B images intact)
    {
        long base = ((long)(mb * 32 + nb) * 256 + tid);
        long stride = 1024L * 256;
        float4 z = make_float4(0.f, 0.f, 0.f, 0.f);
        for (long i = base; i < n4; i += stride) stg_cs4(&out4[i], z);
    }

    for (int s = 0; s < NSTG; ++s) {
        if (s < NSTG - 1) {
            asm volatile("cp.async.wait_group 1;" ::: "memory");
        } else {
            asm volatile("cp.async.wait_group 0;" ::: "memory");
        }
        // single barrier: stage s data visible AND all warps done with
        // compute(s-1), whose buffer (s-1)%3 == (s+2)%3 is refilled below.
        __syncthreads();
        uint32_t st = sb + (s % 3) * STG_BYTES;
        uint32_t aBase = st, bBase = st + 16384;
#pragma unroll
        for (int kk = 0; kk < 4; ++kk) {
            uint32_t af[4][4], bf[4][2];
#pragma unroll
            for (int mt = 0; mt < 4; ++mt)
                lds128(af[mt], aBase + (((wm * 4 + mt) * 4 + kk) * 32 + lane) * 16);
#pragma unroll
            for (int nt = 0; nt < 4; ++nt)
                lds64(bf[nt], bBase + (((wn * 4 + nt) * 4 + kk) * 32 + lane) * 8);
#pragma unroll
            for (int mt = 0; mt < 4; ++mt)
#pragma unroll
                for (int nt = 0; nt < 4; ++nt)
                    mma16(acc[mt][nt], af[mt], bf[nt]);
            if (kk == 0 && s + 2 < NSTG)
                issue_stage(s + 2, mb, nb, sb + ((s + 2) % 3) * STG_BYTES, tid);
        }
    }
    __syncthreads();

    // epilogue: weighted abs row-reduction (r) AND signed M@c (mid) fused
    const int tig = lane & 3, gp = lane >> 2;
#pragma unroll
    for (int mt = 0; mt < 4; ++mt)
#pragma unroll
        for (int hf = 0; hf < 2; ++hf) {
            float p = 0.f, pm = 0.f;
#pragma unroll
            for (int nt = 0; nt < 4; ++nt) {
                int n0 = wn * 32 + nt * 8 + 2 * tig;
                float v0 = acc[mt][nt][hf * 2 + 0];
                float v1 = acc[mt][nt][hf * 2 + 1];
                p += fabsf(v0) * h[n0] + fabsf(v1) * h[n0 + 1];
                pm += v0 * c[n0] + v1 * c[n0 + 1];
            }
            p += __shfl_xor_sync(0xffffffffu, p, 1);
            p += __shfl_xor_sync(0xffffffffu, p, 2);
            pm += __shfl_xor_sync(0xffffffffu, pm, 1);
            pm += __shfl_xor_sync(0xffffffffu, pm, 2);
            if (tig == 0) {
                int idx = (wm * 64 + mt * 16 + hf * 8 + gp) * 4 + wn;
                red[idx] = p;
                red2[idx] = pm;
            }
        }
    __syncthreads();
    if (tid < 128) {
        float vr = red[tid * 4 + 0] + red[tid * 4 + 1] + red[tid * 4 + 2] + red[tid * 4 + 3];
        float vm = red2[tid * 4 + 0] + red2[tid * 4 + 1] + red2[tid * 4 + 2] + red2[tid * 4 + 3];
        g_rpart[nb][mb * 128 + tid] = vr;
        g_mpart[nb][mb * 128 + tid] = vm;
    }
}

// ---------------- finalize: DeepPoly ReLU transformer + scatter ----------
__global__ void k_finalize(const float *__restrict__ raw_alpha,
                           const float *__restrict__ b2,
                           float *__restrict__ out) {
    int i = blockIdx.x * blockDim.x + threadIdx.x;
    if (i >= N) return;
    float r = 0.f, mid = b2[i];
#pragma unroll
    for (int s = 0; s < 32; ++s) {
        r += g_rpart[s][i];
        mid += g_mpart[s][i];
    }
#pragma unroll
    for (int s = 0; s < 8; ++s) mid += g_cipart[s][i];
    float lb = mid - r;
    float ub = mid + r;
    float denom = ub - lb;
    float rs = (denom == 0.f) ? 0.f : ub / denom;
    float rint = (1.f - rs) * ub;
    bool below = (ub <= 0.f);
    bool above = (lb >= 0.f);
    bool crossing = !(below || above);
    float base = above ? 1.f : 0.f;
    float uslope = crossing ? rs : base;
    float uint_ = crossing ? rint : 0.f;
    float v1 = crossing ? 0.f : base;
    float v2 = crossing ? 1.f : base;
    float alpha = 1.f / (1.f + expf(-raw_alpha[i]));
    float lslope = alpha * v1 + (1.f - alpha) * v2;

    const long NN = (long)N * N;
    out[(long)i * N + i] = lslope;               // diag(lslope)
    /* lintercept stays zero */
    out[NN + N + (long)i * N + i] = uslope;      // diag(uslope)
    out[2 * NN + N + i] = uint_;                 // uintercept
}

// --------------------------------------------------------------------------
extern "C" void kernel_launch(void *const *d_in, const int *in_sizes, int n_in,
                              void *d_out, int out_size) {
    const float *raw_alpha = (const float *)d_in[0];
    const float *lb0 = (const float *)d_in[1];
    const float *ub0 = (const float *)d_in[2];
    const float *W1 = (const float *)d_in[3];
    const float *b1 = (const float *)d_in[4];
    const float *W2 = (const float *)d_in[5];
    const float *b2 = (const float *)d_in[6];
    float *out = (float *)d_out;

    cudaFuncSetAttribute(k_gemm, cudaFuncAttributeMaxDynamicSharedMemorySize, GSMEM);

    k_pre<<<4096, 256>>>(W2, b1, W1);
    dim3 gg(32, 32);
    k_gemm<<<gg, 256, GSMEM>>>(lb0, ub0, (float4 *)out, (long)out_size / 4);
    k_finalize<<<N / 256, 256>>>(raw_alpha, b2, out);
}